// round 4
// baseline (speedup 1.0000x reference)
#include <cuda_runtime.h>
#include <cuda_bf16.h>

// Degenerate BiLSTM: h=c=0 always => only emb[:,S-1] (fwd) and emb[:,0] (bwd)
// matter; the f-gate is dead (c=0); Whf/Whb contribute nothing.
//   B=128, S=2048, EMB=128, HID=256 (4H=1024), OUT=32
//
// Single fused kernel, 128 blocks = 32 h-chunks x 4 batch-groups.
// Each block: gather x -> 3-gate GEMV per direction -> hy in regs ->
// partial logits over its 8 h -> STG. Last block per batch-group (monotonic
// atomic counter, (old&31)==31, works across graph replays with no reset)
// reduces the 32 partials, adds by, and does the 32-wide log-softmax.

#define NB_B   128
#define NB_S   2048
#define NB_EMB 128
#define NB_HID 256
#define NB_OUT 32

// Partial logits: [hc(32)][bg(4)][b(32)*32+o]  (512 KB)
__device__ float g_part[32 * 4 * 32 * 32];
__device__ unsigned int g_cnt[4];   // monotonic; 32 increments per bg per launch

__device__ __forceinline__ float sigm(float x) { return 1.0f / (1.0f + expf(-x)); }

__global__ void __launch_bounds__(256, 1) bilstm_fused_kernel(
    const int*   __restrict__ inputs,   // [B, S]
    const float* __restrict__ weight,   // [VOCAB, EMB]
    const float* __restrict__ Wxf,      // [1024, 128]
    const float* __restrict__ bxf,
    const float* __restrict__ bhf,
    const float* __restrict__ Wxb,
    const float* __restrict__ bxb,
    const float* __restrict__ bhb,
    const float* __restrict__ Why,      // [32, 256]
    const float* __restrict__ by,       // [32]
    float*       __restrict__ out)      // [B, 32]
{
    // Phase A: xs[(dir*128+e)*33 + lb]  (2*128*33 = 8448 floats, 33.8 KB)
    // Phase B (reuse): sp[hl*1056 + o*33 + lb] (8*32*33 = 8448 floats)
    __shared__ float smem[2 * NB_EMB * 33];
    __shared__ int   tok_s[64];
    __shared__ int   isLast;

    const int tid    = threadIdx.x;
    const int hc     = blockIdx.x & 31;
    const int bg     = blockIdx.x >> 5;
    const int h_base = hc * 8;
    const int b_base = bg * 32;

    if (tid < 64) {
        const int dir = tid >> 5;
        const int lb  = tid & 31;
        tok_s[tid] = inputs[(b_base + lb) * NB_S + (dir ? 0 : (NB_S - 1))];
    }
    __syncthreads();

    // Gather embeddings, transposed into shared: LDG coalesced over e,
    // STS stride-33 across lanes -> conflict-free.
    for (int idx = tid; idx < 2 * 32 * NB_EMB; idx += 256) {
        const int dir = idx >> 12;
        const int lb  = (idx >> 7) & 31;
        const int e   = idx & 127;
        const int tok = tok_s[dir * 32 + lb];
        smem[(dir * NB_EMB + e) * 33 + lb] = weight[tok * NB_EMB + e];
    }
    __syncthreads();

    const int hl = tid >> 5;   // warp = local h
    const int lb = tid & 31;   // lane = local batch
    const int h  = h_base + hl;

    const float* xf = smem + lb;                 // xf[e*33]
    const float* xb = smem + NB_EMB * 33 + lb;   // xb[e*33]

    const float4* wif = (const float4*)(Wxf + (h)       * NB_EMB);
    const float4* wgf = (const float4*)(Wxf + (512 + h) * NB_EMB);
    const float4* wof = (const float4*)(Wxf + (768 + h) * NB_EMB);
    const float4* wib = (const float4*)(Wxb + (h)       * NB_EMB);
    const float4* wgb = (const float4*)(Wxb + (512 + h) * NB_EMB);
    const float4* wob = (const float4*)(Wxb + (768 + h) * NB_EMB);

    float aif = 0.f, agf = 0.f, aof = 0.f;
    float aib = 0.f, agb = 0.f, aob = 0.f;

    #pragma unroll 8
    for (int k4 = 0; k4 < NB_EMB / 4; k4++) {
        const int e = k4 * 4;
        // conflict-free scalar LDS (bank = (e+lb) mod 32)
        const float a0 = xf[(e + 0) * 33], a1 = xf[(e + 1) * 33];
        const float a2 = xf[(e + 2) * 33], a3 = xf[(e + 3) * 33];
        const float c0 = xb[(e + 0) * 33], c1 = xb[(e + 1) * 33];
        const float c2 = xb[(e + 2) * 33], c3 = xb[(e + 3) * 33];
        float4 w;
        w = wif[k4];
        aif = fmaf(w.x, a0, fmaf(w.y, a1, fmaf(w.z, a2, fmaf(w.w, a3, aif))));
        w = wgf[k4];
        agf = fmaf(w.x, a0, fmaf(w.y, a1, fmaf(w.z, a2, fmaf(w.w, a3, agf))));
        w = wof[k4];
        aof = fmaf(w.x, a0, fmaf(w.y, a1, fmaf(w.z, a2, fmaf(w.w, a3, aof))));
        w = wib[k4];
        aib = fmaf(w.x, c0, fmaf(w.y, c1, fmaf(w.z, c2, fmaf(w.w, c3, aib))));
        w = wgb[k4];
        agb = fmaf(w.x, c0, fmaf(w.y, c1, fmaf(w.z, c2, fmaf(w.w, c3, agb))));
        w = wob[k4];
        aob = fmaf(w.x, c0, fmaf(w.y, c1, fmaf(w.z, c2, fmaf(w.w, c3, aob))));
    }

    const float gif = aif + bxf[h]       + bhf[h];
    const float ggf = agf + bxf[512 + h] + bhf[512 + h];
    const float gof = aof + bxf[768 + h] + bhf[768 + h];
    const float gib = aib + bxb[h]       + bhb[h];
    const float ggb = agb + bxb[512 + h] + bhb[512 + h];
    const float gob = aob + bxb[768 + h] + bhb[768 + h];

    const float hyv = sigm(gof) * tanhf(sigm(gif) * tanhf(ggf))
                    + sigm(gob) * tanhf(sigm(gib) * tanhf(ggb));

    // ---- partial logits over this block's 8 h values ----
    __syncthreads();                 // xs reads done; reuse smem as sp
    float* sp = smem;                // sp[hl*1056 + o*33 + lb]

    #pragma unroll
    for (int o = 0; o < NB_OUT; o++) {
        const float wv = Why[o * NB_HID + h];        // lane-uniform broadcast
        sp[hl * 1056 + o * 33 + lb] = hyv * wv;      // CF STS
    }
    __syncthreads();

    // Reduce over the 8 warps: thread handles p = tid + 256*i  (p = b*32+o)
    float* part = g_part + (hc * 4 + bg) * 1024;
    #pragma unroll
    for (int i = 0; i < 4; i++) {
        const int p   = tid + 256 * i;
        const int plb = p >> 5;
        const int po  = p & 31;
        float s = 0.f;
        #pragma unroll
        for (int w8 = 0; w8 < 8; w8++)
            s += sp[w8 * 1056 + po * 33 + plb];      // CF LDS
        part[p] = s;                                 // coalesced STG
    }

    // ---- last-arriver election per batch-group ----
    __threadfence();
    __syncthreads();
    if (tid == 0) {
        const unsigned int old = atomicAdd(&g_cnt[bg], 1u);
        isLast = ((old & 31u) == 31u);
    }
    __syncthreads();
    if (!isLast) return;

    // ---- tail: reduce 32 partials + bias, 32-wide log-softmax ----
    __threadfence();
    const int o = tid & 31;          // lane = output
    const int w = tid >> 5;          // warp = 4 batches
    const float bias = by[o];

    #pragma unroll
    for (int i = 0; i < 4; i++) {
        const int b = w * 4 + i;
        float acc = bias;
        #pragma unroll
        for (int c = 0; c < 32; c++)
            acc += __ldcg(&g_part[(c * 4 + bg) * 1024 + b * 32 + o]);

        float mx = acc;
        #pragma unroll
        for (int off = 16; off; off >>= 1)
            mx = fmaxf(mx, __shfl_xor_sync(0xffffffffu, mx, off));
        float s = expf(acc - mx);
        #pragma unroll
        for (int off = 16; off; off >>= 1)
            s += __shfl_xor_sync(0xffffffffu, s, off);

        out[(b_base + b) * NB_OUT + o] = acc - mx - logf(s);
    }
}

// Inputs in metadata order:
// 0 inputs(int32) 1 weight 2 Wxf 3 bxf 4 Whf(unused) 5 bhf
// 6 Wxb 7 bxb 8 Whb(unused) 9 bhb 10 Why 11 by
extern "C" void kernel_launch(void* const* d_in, const int* in_sizes, int n_in,
                              void* d_out, int out_size)
{
    const int*   inputs = (const int*)  d_in[0];
    const float* weight = (const float*)d_in[1];
    const float* Wxf    = (const float*)d_in[2];
    const float* bxf    = (const float*)d_in[3];
    const float* bhf    = (const float*)d_in[5];
    const float* Wxb    = (const float*)d_in[6];
    const float* bxb    = (const float*)d_in[7];
    const float* bhb    = (const float*)d_in[9];
    const float* Why    = (const float*)d_in[10];
    const float* by     = (const float*)d_in[11];
    float*       out    = (float*)d_out;

    bilstm_fused_kernel<<<128, 256>>>(inputs, weight, Wxf, bxf, bhf,
                                      Wxb, bxb, bhb, Why, by, out);
}